// round 15
// baseline (speedup 1.0000x reference)
#include <cuda_runtime.h>
#include <cuda_fp16.h>
#include <cstdint>
#include <cstddef>

#define NR 8192
#define DD 512
#define LSHIFT 6.931472f   // ~ln(1024): centers logits near 0 for fp16 storage

// ---------------------------------------------------------------------------
// Device scratch (static — no cudaMalloc allowed)
// ---------------------------------------------------------------------------
__device__ __half g_l[(size_t)NR * NR];        // 134 MB: logit + LSHIFT, fp16
__device__ float  g_dd2[NR];                   // exact fp32 diagonal d2
__device__ __half g_ca[(size_t)NR * DD];       // fp16-rounded context
__device__ __half g_tb[(size_t)NR * DD];       // fp16-rounded target
__device__ float  g_c2[NR];                    // ||c_h||^2 of rounded values
__device__ float  g_t2[NR];
// [0]=S_exp_off [1]=sum_logit_diag [2]=sum_sig_diag [3]=cnt_diag
// [4]=sum_logit_all [5]=sum_sig_all [6]=cnt_all [7]=log_baseline
__device__ double g_acc[16];
__device__ double g_sexp_bucket[64];
__device__ double g_slog_bucket[64];
__device__ unsigned int g_ticket_gemm;
__device__ unsigned int g_ticket_stream;

// ---------------------------------------------------------------------------
// helpers
// ---------------------------------------------------------------------------
__device__ __forceinline__ uint32_t smem_u32(const void* p) {
    uint32_t a;
    asm("{ .reg .u64 t; cvta.to.shared.u64 t, %1; cvt.u32.u64 %0, t; }"
        : "=r"(a) : "l"(p));
    return a;
}

#define LDSM_X4(r0, r1, r2, r3, addr)                                   \
    asm volatile("ldmatrix.sync.aligned.m8n8.x4.shared.b16 "            \
                 "{%0,%1,%2,%3}, [%4];"                                 \
                 : "=r"(r0), "=r"(r1), "=r"(r2), "=r"(r3) : "r"(addr))

#define MMA_F16(d, a0, a1, a2, a3, b0, b1)                              \
    asm volatile("mma.sync.aligned.m16n8k16.row.col.f32.f16.f16.f32 "   \
                 "{%0,%1,%2,%3}, {%4,%5,%6,%7}, {%8,%9}, {%0,%1,%2,%3};"\
                 : "+f"((d)[0]), "+f"((d)[1]), "+f"((d)[2]), "+f"((d)[3])\
                 : "r"(a0), "r"(a1), "r"(a2), "r"(a3), "r"(b0), "r"(b1))

// ---------------------------------------------------------------------------
// 0) zero accumulators
// ---------------------------------------------------------------------------
__global__ void k_init() {
    if (threadIdx.x < 16) g_acc[threadIdx.x] = 0.0;
    if (threadIdx.x < 64) { g_sexp_bucket[threadIdx.x] = 0.0; g_slog_bucket[threadIdx.x] = 0.0; }
    if (threadIdx.x == 0) { g_ticket_gemm = 0u; g_ticket_stream = 0u; }
}

// ---------------------------------------------------------------------------
// 1) fused prep: each block handles row i of BOTH C and T.
//    fp16-rounded copies, squared norms of rounded values, diagonal d2
//    (directly from registers — no global re-read).
// ---------------------------------------------------------------------------
__global__ void k_prepCT(const float* __restrict__ C, const float* __restrict__ T) {
    int row = blockIdx.x;

    float4 vc = ((const float4*)(C + (size_t)row * DD))[threadIdx.x];
    __half2 hc0 = __floats2half2_rn(vc.x, vc.y);
    __half2 hc1 = __floats2half2_rn(vc.z, vc.w);
    ((uint2*)(g_ca + (size_t)row * DD))[threadIdx.x] =
        make_uint2(*(uint32_t*)&hc0, *(uint32_t*)&hc1);

    float4 vt = ((const float4*)(T + (size_t)row * DD))[threadIdx.x];
    __half2 ht0 = __floats2half2_rn(vt.x, vt.y);
    __half2 ht1 = __floats2half2_rn(vt.z, vt.w);
    ((uint2*)(g_tb + (size_t)row * DD))[threadIdx.x] =
        make_uint2(*(uint32_t*)&ht0, *(uint32_t*)&ht1);

    float2 c0 = __half22float2(hc0), c1 = __half22float2(hc1);
    float2 t0 = __half22float2(ht0), t1 = __half22float2(ht1);

    float sc = c0.x * c0.x + c0.y * c0.y + c1.x * c1.x + c1.y * c1.y;
    float st = t0.x * t0.x + t0.y * t0.y + t1.x * t1.x + t1.y * t1.y;
    float e0 = c0.x - t0.x, e1 = c0.y - t0.y;
    float e2 = c1.x - t1.x, e3 = c1.y - t1.y;
    float d  = e0 * e0 + e1 * e1 + e2 * e2 + e3 * e3;

    #pragma unroll
    for (int o = 16; o > 0; o >>= 1) {
        sc += __shfl_down_sync(0xffffffffu, sc, o);
        st += __shfl_down_sync(0xffffffffu, st, o);
        d  += __shfl_down_sync(0xffffffffu, d, o);
    }
    __shared__ float wc[4], wt[4], wd[4];
    if ((threadIdx.x & 31) == 0) {
        wc[threadIdx.x >> 5] = sc; wt[threadIdx.x >> 5] = st; wd[threadIdx.x >> 5] = d;
    }
    __syncthreads();
    if (threadIdx.x == 0) {
        g_c2[row]  = wc[0] + wc[1] + wc[2] + wc[3];
        g_t2[row]  = wt[0] + wt[1] + wt[2] + wt[3];
        g_dd2[row] = wd[0] + wd[1] + wd[2] + wd[3];
    }
}

// ---------------------------------------------------------------------------
// 2) fp16 mma.sync GEMM (C @ T^T), 128x128x64 CTA tile, 128 threads,
//    4 warps (2x2) of 64x64, fp32-acc MMA (R11 core, unchanged).
//    Last-CTA ticket runs the "mid" phase (LB + diagonal stats) in-kernel.
// ---------------------------------------------------------------------------
#define NSTAGE 3
#define STAGE_BYTES 32768                       // A 16KB + B 16KB
#define SMEM_DYN (NSTAGE * STAGE_BYTES)         // 96 KB
#define NCHUNK 8                                // 512 / 64
#define NCTAS  ((NR / 128) * (NR / 128))        // 4096

__global__ __launch_bounds__(128, 2)
void k_gemm_tc() {
    extern __shared__ char dsm[];
    const uint32_t smb = smem_u32(dsm);
    const int tid  = threadIdx.x;
    const int wid  = tid >> 5;
    const int lane = tid & 31;
    const int warp_m = wid >> 1;                // 0..1 (64 rows each)
    const int warp_n = wid & 1;                 // 0..1 (64 cols each)
    const int brow = blockIdx.y * 128;
    const int bcol = blockIdx.x * 128;

    const __half* A = g_ca;
    const __half* B = g_tb;

    float acc[4][8][4];
    #pragma unroll
    for (int i = 0; i < 4; i++)
        #pragma unroll
        for (int j = 0; j < 8; j++)
            #pragma unroll
            for (int d = 0; d < 4; d++) acc[i][j][d] = 0.0f;

    const int lr = tid >> 3;                    // 0..15
    const int lq = tid & 7;                     // 16B segment within 128B row
    auto issue_chunk = [&](int c) {
        const int s = c % NSTAGE;
        const uint32_t sA = smb + s * STAGE_BYTES;
        const uint32_t sB = sA + 16384;
        const __half* gA = A + (size_t)brow * DD + c * 64;
        const __half* gB = B + (size_t)bcol * DD + c * 64;
        #pragma unroll
        for (int i = 0; i < 8; i++) {
            int r = i * 16 + lr;
            uint32_t off = (uint32_t)(r * 128) + (uint32_t)(((lq ^ (r & 7)) << 4));
            const __half* pA = gA + (size_t)r * DD + lq * 8;
            const __half* pB = gB + (size_t)r * DD + lq * 8;
            asm volatile("cp.async.cg.shared.global [%0], [%1], 16;"
                         :: "r"(sA + off), "l"(pA) : "memory");
            asm volatile("cp.async.cg.shared.global [%0], [%1], 16;"
                         :: "r"(sB + off), "l"(pB) : "memory");
        }
        asm volatile("cp.async.commit_group;" ::: "memory");
    };

    const int t8 = lane >> 3;
    const int r8 = lane & 7;
    uint32_t aoff[4], boff[4];
    #pragma unroll
    for (int mf = 0; mf < 4; mf++)
        aoff[mf] = (uint32_t)((warp_m * 64 + mf * 16 + (t8 & 1) * 8 + r8) * 128);
    #pragma unroll
    for (int nf4 = 0; nf4 < 4; nf4++)
        boff[nf4] = (uint32_t)((warp_n * 64 + nf4 * 16 + (t8 >> 1) * 8 + r8) * 128) + 16384u;
    const int xa = (t8 >> 1);                   // A: k-half selector
    const int xb = (t8 & 1);                    // B: k-half selector

    issue_chunk(0); issue_chunk(1);
    asm volatile("cp.async.wait_group 1;" ::: "memory");
    __syncthreads();

    for (int c = 0; c < NCHUNK; c++) {
        if (c + 2 < NCHUNK) issue_chunk(c + 2);

        const uint32_t base = smb + (c % NSTAGE) * STAGE_BYTES;

        #pragma unroll
        for (int ks = 0; ks < 4; ks++) {        // 4 x k16 = 64
            const uint32_t sgA = (uint32_t)(((ks * 2 + xa) ^ r8) << 4);
            const uint32_t sgB = (uint32_t)(((ks * 2 + xb) ^ r8) << 4);
            uint32_t b[8][2];
            #pragma unroll
            for (int nf4 = 0; nf4 < 4; nf4++)
                LDSM_X4(b[nf4 * 2][0], b[nf4 * 2][1],
                        b[nf4 * 2 + 1][0], b[nf4 * 2 + 1][1],
                        base + boff[nf4] + sgB);

            uint32_t acur[4], anxt[4];
            LDSM_X4(acur[0], acur[1], acur[2], acur[3], base + aoff[0] + sgA);
            #pragma unroll
            for (int mf = 0; mf < 4; mf++) {
                if (mf < 3)
                    LDSM_X4(anxt[0], anxt[1], anxt[2], anxt[3],
                            base + aoff[mf + 1] + sgA);
                #pragma unroll
                for (int nf = 0; nf < 8; nf++)
                    MMA_F16(acc[mf][nf],
                            acur[0], acur[1], acur[2], acur[3],
                            b[nf][0], b[nf][1]);
                #pragma unroll
                for (int k2 = 0; k2 < 4; k2++) acur[k2] = anxt[k2];
            }
        }

        if (c < NCHUNK - 2) {
            asm volatile("cp.async.wait_group 1;" ::: "memory");
            __syncthreads();
        } else if (c == NCHUNK - 2) {
            asm volatile("cp.async.wait_group 0;" ::: "memory");
            __syncthreads();
        }
    }

    // ----- epilogue: ALL-inclusive sums, no diagonal branches -----
    const int g = lane >> 2;                    // row within frag half
    const int q = lane & 3;                     // col pair
    float c2v[8];
    #pragma unroll
    for (int mf = 0; mf < 4; mf++) {
        c2v[mf * 2]     = g_c2[brow + warp_m * 64 + mf * 16 + g];
        c2v[mf * 2 + 1] = g_c2[brow + warp_m * 64 + mf * 16 + 8 + g];
    }
    float t2v[16];
    #pragma unroll
    for (int nf = 0; nf < 8; nf++) {
        t2v[nf * 2]     = g_t2[bcol + warp_n * 64 + nf * 8 + q * 2];
        t2v[nf * 2 + 1] = g_t2[bcol + warp_n * 64 + nf * 8 + q * 2 + 1];
    }

    float sexp = 0.0f;     // ALL-inclusive sum of p = 1/(1+d2)
    float slog = 0.0f;     // ALL-inclusive sum of logit = -log(1+d2)
    #pragma unroll
    for (int mf = 0; mf < 4; mf++) {
        #pragma unroll
        for (int h = 0; h < 2; h++) {
            const int row = brow + warp_m * 64 + mf * 16 + h * 8 + g;
            #pragma unroll
            for (int nf = 0; nf < 8; nf++) {
                const int col = bcol + warp_n * 64 + nf * 8 + q * 2;
                float dot0 = acc[mf][nf][h * 2];
                float dot1 = acc[mf][nf][h * 2 + 1];
                float u0 = fmaxf(c2v[mf * 2 + h] + t2v[nf * 2]     - 2.0f * dot0, 0.0f) + 1.0f;
                float u1 = fmaxf(c2v[mf * 2 + h] + t2v[nf * 2 + 1] - 2.0f * dot1, 0.0f) + 1.0f;
                float lg0 = -__logf(u0);
                float lg1 = -__logf(u1);
                slog += lg0 + lg1;
                sexp += __fdividef(1.0f, u0);
                sexp += __fdividef(1.0f, u1);
                *(__half2*)&g_l[(size_t)row * NR + col] =
                    __floats2half2_rn(lg0 + LSHIFT, lg1 + LSHIFT);
            }
        }
    }

    // reduce (sexp, slog): warp -> CTA -> bucketed atomic
    double se = (double)sexp;
    double sl = (double)slog;
    #pragma unroll
    for (int o = 16; o > 0; o >>= 1) {
        se += __shfl_down_sync(0xffffffffu, se, o);
        sl += __shfl_down_sync(0xffffffffu, sl, o);
    }
    double* red = (double*)dsm;
    __syncthreads();
    if (lane == 0) { red[wid] = se; red[4 + wid] = sl; }
    __syncthreads();

    __shared__ unsigned int s_t;
    if (tid == 0) {
        double t0 = 0.0, t1 = 0.0;
        #pragma unroll
        for (int w = 0; w < 4; w++) { t0 += red[w]; t1 += red[4 + w]; }
        int bk = (blockIdx.y * 64 + blockIdx.x) & 63;
        atomicAdd(&g_sexp_bucket[bk], t0);
        atomicAdd(&g_slog_bucket[bk], t1);
        __threadfence();
        s_t = atomicAdd(&g_ticket_gemm, 1u);
    }
    __syncthreads();

    // ----- last CTA: mid phase (LB + diagonal stats) -----
    if (s_t == (unsigned int)(NCTAS - 1)) {
        __threadfence();                        // acquire other CTAs' bucket writes
        double* m0 = (double*)dsm;              // 128 doubles
        double* m1 = m0 + 128;                  // 128 doubles
        int*    m2 = (int*)(m1 + 128);          // 128 ints
        float*  mf_lb = (float*)(m2 + 128);

        double s = (tid < 64) ? g_sexp_bucket[tid] : 0.0;
        double l = (tid < 64) ? g_slog_bucket[tid] : 0.0;
        float sub = 0.0f;                       // sum of diagonal p
        for (int i = tid; i < NR; i += 128)
            sub += __fdividef(1.0f, 1.0f + g_dd2[i]);
        s -= (double)sub;

        m0[tid] = s; m1[tid] = l;
        __syncthreads();
        for (int st = 64; st > 0; st >>= 1) {
            if (tid < st) { m0[tid] += m0[tid + st]; m1[tid] += m1[tid + st]; }
            __syncthreads();
        }
        if (tid == 0) {
            double lb = log(m0[0]) - log((double)NR * (double)(NR - 1));
            g_acc[0] = m0[0];                   // S_exp over off-diagonal
            g_acc[4] = m1[0];                   // sum logit (all incl diag)
            g_acc[7] = lb;
            mf_lb[0] = (float)lb;
        }
        __syncthreads();

        const float lbf = mf_lb[0];
        float dslog = 0.0f, dssig = 0.0f;
        int dcnt = 0;
        for (int i = tid; i < NR; i += 128) {
            float d2 = g_dd2[i];
            float x = -log1pf(d2);
            float y = x - lbf;
            dslog += x;
            dssig += 1.0f / (1.0f + expf(-y));
            dcnt  += (y > 0.0f) ? 1 : 0;
        }
        __syncthreads();
        m0[tid] = (double)dslog; m1[tid] = (double)dssig; m2[tid] = dcnt;
        __syncthreads();
        for (int st = 64; st > 0; st >>= 1) {
            if (tid < st) { m0[tid] += m0[tid + st]; m1[tid] += m1[tid + st]; m2[tid] += m2[tid + st]; }
            __syncthreads();
        }
        if (tid == 0) {
            g_acc[1] = m0[0]; g_acc[2] = m1[0]; g_acc[3] = (double)m2[0];
        }
    }
}

// ---------------------------------------------------------------------------
// 3) streaming stats over all shifted logits (fp16) + last-block finalize.
// ---------------------------------------------------------------------------
#define STREAM_BLOCKS 4096

__global__ __launch_bounds__(256)
void k_stream(float* __restrict__ out) {
    const float thrf = (float)g_acc[7] + LSHIFT;
    const __half2 thr2 = __float2half2_rn(thrf);
    const __half2 one2 = __float2half2_rn(1.0f);
    const int tid = threadIdx.x;

    float  ssig = 0.0f;
    int    cnt = 0;
    const size_t total8 = ((size_t)NR * NR) / 8;          // uint4 = 8 halves
    const size_t stride = (size_t)gridDim.x * blockDim.x;
    const uint4* P8 = (const uint4*)g_l;

    for (size_t i = (size_t)blockIdx.x * blockDim.x + tid; i < total8; i += stride) {
        uint4 v = __ldcs(&P8[i]);
        uint32_t w[4] = {v.x, v.y, v.z, v.w};
        #pragma unroll
        for (int j = 0; j < 4; j++) {
            __half2 hj = *(__half2*)&w[j];
            __half2 y  = __hsub2(hj, thr2);
            __half2 e  = h2exp(__hneg2(y));
            __half2 sg = h2rcp(__hadd2(one2, e));
            float2 sf = __half22float2(sg);
            ssig += sf.x + sf.y;
            float2 yf = __half22float2(y);
            cnt += (yf.x > 0.0f) + (yf.y > 0.0f);
        }
    }

    __shared__ double r1[256];
    __shared__ int    r2[256];
    r1[tid] = (double)ssig; r2[tid] = cnt;
    __syncthreads();
    for (int s = 128; s > 0; s >>= 1) {
        if (tid < s) { r1[tid] += r1[tid + s]; r2[tid] += r2[tid + s]; }
        __syncthreads();
    }

    __shared__ int s_last;
    if (tid == 0) {
        atomicAdd(&g_acc[5], r1[0]);
        atomicAdd(&g_acc[6], (double)r2[0]);
        __threadfence();
        unsigned int t = atomicAdd(&g_ticket_stream, 1u);
        s_last = (t == (unsigned int)(gridDim.x - 1)) ? 1 : 0;
    }
    __syncthreads();

    if (s_last && tid == 0) {
        __threadfence();
        const double Npos = (double)NR;
        const double Nneg = (double)NR * (double)(NR - 1);

        double LB   = g_acc[7];
        double sdl  = g_acc[1];
        double sds  = g_acc[2];
        double cntd = g_acc[3];
        double sal  = g_acc[4];
        double sas  = g_acc[5];
        double cnta = g_acc[6];

        double pos_mean  = sdl / Npos - LB;
        double neg_mean  = (sal - sdl) / Nneg - LB;
        double repulsion = exp(-LB) * g_acc[0] / Nneg;
        double loss      = -pos_mean + repulsion;
        double sig_pos   = sds / Npos;
        double sig_neg   = (sas - sds) / Nneg;

        double TP = cntd / Npos;
        double FP = (cnta - cntd) / Nneg;
        double TN = 1.0 - FP;
        double FN = 1.0 - TP;
        double accuracy  = (TP + TN) * 0.5;
        double precision = TP / (TP + FP);
        double npv       = TN / (TN + FN);
        double apv       = (precision + npv) * 0.5;

        out[0]  = (float)loss;
        out[1]  = (float)pos_mean;
        out[2]  = (float)neg_mean;
        out[3]  = (float)sig_pos;
        out[4]  = (float)sig_neg;
        out[5]  = (float)LB;
        out[6]  = (float)accuracy;
        out[7]  = (float)precision;
        out[8]  = (float)npv;
        out[9]  = (float)apv;
        out[10] = (float)TP;
        out[11] = (float)TN;
    }
}

// ---------------------------------------------------------------------------
// launch
// ---------------------------------------------------------------------------
extern "C" void kernel_launch(void* const* d_in, const int* in_sizes, int n_in,
                              void* d_out, int out_size) {
    const float* C = (const float*)d_in[0];
    const float* T = (const float*)d_in[1];
    float* out = (float*)d_out;

    static int configured = 0;
    if (!configured) {
        cudaFuncSetAttribute(k_gemm_tc, cudaFuncAttributeMaxDynamicSharedMemorySize, SMEM_DYN);
        configured = 1;
    }

    k_init<<<1, 64>>>();                         // launch 0
    k_prepCT<<<NR, 128>>>(C, T);                 // launch 1
    dim3 grid(NR / 128, NR / 128);
    k_gemm_tc<<<grid, 128, SMEM_DYN>>>();        // launch 2 (mid fused)
    k_stream<<<STREAM_BLOCKS, 256>>>(out);       // launch 3 (finalize fused) <- ncu slot
}

// round 16
// speedup vs baseline: 1.1549x; 1.1549x over previous
#include <cuda_runtime.h>
#include <cuda_fp16.h>
#include <cstdint>
#include <cstddef>

#define NR 8192
#define DD 512
#define LSHIFT 6.931472f   // ~ln(1024): centers logits near 0 for fp16 storage

// ---------------------------------------------------------------------------
// Device scratch (static — no cudaMalloc allowed)
// ---------------------------------------------------------------------------
__device__ __half g_l[(size_t)NR * NR];        // 134 MB: logit + LSHIFT, fp16
__device__ float  g_dd2[NR];                   // exact fp32 diagonal d2
__device__ __half g_ca[(size_t)NR * DD];       // fp16-rounded context
__device__ __half g_tb[(size_t)NR * DD];       // fp16-rounded target
__device__ float  g_c2[NR];                    // ||c_h||^2 of rounded values
__device__ float  g_t2[NR];
// [0]=S_exp_off [1]=sum_logit_diag [2]=sum_sig_diag [3]=cnt_diag
// [4]=sum_logit_all [5]=sum_sig_all [6]=cnt_all [7]=log_baseline
__device__ double g_acc[16];
__device__ double g_sexp_bucket[64];
__device__ double g_slog_bucket[64];
__device__ unsigned int g_ticket;

// ---------------------------------------------------------------------------
// helpers
// ---------------------------------------------------------------------------
__device__ __forceinline__ uint32_t smem_u32(const void* p) {
    uint32_t a;
    asm("{ .reg .u64 t; cvta.to.shared.u64 t, %1; cvt.u32.u64 %0, t; }"
        : "=r"(a) : "l"(p));
    return a;
}

#define LDSM_X4(r0, r1, r2, r3, addr)                                   \
    asm volatile("ldmatrix.sync.aligned.m8n8.x4.shared.b16 "            \
                 "{%0,%1,%2,%3}, [%4];"                                 \
                 : "=r"(r0), "=r"(r1), "=r"(r2), "=r"(r3) : "r"(addr))

#define MMA_F16(d, a0, a1, a2, a3, b0, b1)                              \
    asm volatile("mma.sync.aligned.m16n8k16.row.col.f32.f16.f16.f32 "   \
                 "{%0,%1,%2,%3}, {%4,%5,%6,%7}, {%8,%9}, {%0,%1,%2,%3};"\
                 : "+f"((d)[0]), "+f"((d)[1]), "+f"((d)[2]), "+f"((d)[3])\
                 : "r"(a0), "r"(a1), "r"(a2), "r"(a3), "r"(b0), "r"(b1))

// ---------------------------------------------------------------------------
// 0) zero accumulators
// ---------------------------------------------------------------------------
__global__ void k_init() {
    if (threadIdx.x < 16) g_acc[threadIdx.x] = 0.0;
    if (threadIdx.x < 64) { g_sexp_bucket[threadIdx.x] = 0.0; g_slog_bucket[threadIdx.x] = 0.0; }
    if (threadIdx.x == 0) g_ticket = 0u;
}

// ---------------------------------------------------------------------------
// 1a) prep C: fp16-rounded copy + squared norm of rounded values
// ---------------------------------------------------------------------------
__global__ void k_prepC(const float* __restrict__ C) {
    int row = blockIdx.x;
    float4 v = ((const float4*)(C + (size_t)row * DD))[threadIdx.x];
    __half2 h0 = __floats2half2_rn(v.x, v.y);
    __half2 h1 = __floats2half2_rn(v.z, v.w);
    ((uint2*)(g_ca + (size_t)row * DD))[threadIdx.x] =
        make_uint2(*(uint32_t*)&h0, *(uint32_t*)&h1);

    float2 f0 = __half22float2(h0);
    float2 f1 = __half22float2(h1);
    float s = f0.x * f0.x + f0.y * f0.y + f1.x * f1.x + f1.y * f1.y;

    #pragma unroll
    for (int o = 16; o > 0; o >>= 1) s += __shfl_down_sync(0xffffffffu, s, o);
    __shared__ float ws[4];
    if ((threadIdx.x & 31) == 0) ws[threadIdx.x >> 5] = s;
    __syncthreads();
    if (threadIdx.x == 0) g_c2[row] = ws[0] + ws[1] + ws[2] + ws[3];
}

// ---------------------------------------------------------------------------
// 1b) prep T: fp16-rounded copy + squared norm + diagonal d2 = ||c_i - t_i||^2
// ---------------------------------------------------------------------------
__global__ void k_prepT(const float* __restrict__ T) {
    int row = blockIdx.x;
    float4 v = ((const float4*)(T + (size_t)row * DD))[threadIdx.x];
    __half2 h0 = __floats2half2_rn(v.x, v.y);
    __half2 h1 = __floats2half2_rn(v.z, v.w);
    ((uint2*)(g_tb + (size_t)row * DD))[threadIdx.x] =
        make_uint2(*(uint32_t*)&h0, *(uint32_t*)&h1);

    float2 f0 = __half22float2(h0);
    float2 f1 = __half22float2(h1);
    float s = f0.x * f0.x + f0.y * f0.y + f1.x * f1.x + f1.y * f1.y;

    uint2 cu = ((const uint2*)(g_ca + (size_t)row * DD))[threadIdx.x];
    float2 c0 = __half22float2(*(__half2*)&cu.x);
    float2 c1 = __half22float2(*(__half2*)&cu.y);
    float e0 = c0.x - f0.x, e1 = c0.y - f0.y;
    float e2 = c1.x - f1.x, e3 = c1.y - f1.y;
    float d = e0 * e0 + e1 * e1 + e2 * e2 + e3 * e3;

    #pragma unroll
    for (int o = 16; o > 0; o >>= 1) {
        s += __shfl_down_sync(0xffffffffu, s, o);
        d += __shfl_down_sync(0xffffffffu, d, o);
    }
    __shared__ float ws[4], wd[4];
    if ((threadIdx.x & 31) == 0) { ws[threadIdx.x >> 5] = s; wd[threadIdx.x >> 5] = d; }
    __syncthreads();
    if (threadIdx.x == 0) {
        g_t2[row]  = ws[0] + ws[1] + ws[2] + ws[3];
        g_dd2[row] = wd[0] + wd[1] + wd[2] + wd[3];
    }
}

// ---------------------------------------------------------------------------
// 2) fp16 mma.sync GEMM (C @ T^T), 128x128x64 CTA tile, 128 threads,
//    4 warps (2x2) of 64x64. Single-sync software pipeline + A-frag pipelining.
//    (EXACT R11-best mainloop — protected asset, 235.7 us measured.)
// ---------------------------------------------------------------------------
#define NSTAGE 3
#define STAGE_BYTES 32768                       // A 16KB + B 16KB
#define SMEM_DYN (NSTAGE * STAGE_BYTES)         // 96 KB
#define NCHUNK 8                                // 512 / 64

__global__ __launch_bounds__(128, 2)
void k_gemm_tc() {
    extern __shared__ char dsm[];
    const uint32_t smb = smem_u32(dsm);
    const int tid  = threadIdx.x;
    const int wid  = tid >> 5;
    const int lane = tid & 31;
    const int warp_m = wid >> 1;                // 0..1 (64 rows each)
    const int warp_n = wid & 1;                 // 0..1 (64 cols each)
    const int brow = blockIdx.y * 128;
    const int bcol = blockIdx.x * 128;

    const __half* A = g_ca;
    const __half* B = g_tb;

    float acc[4][8][4];
    #pragma unroll
    for (int i = 0; i < 4; i++)
        #pragma unroll
        for (int j = 0; j < 8; j++)
            #pragma unroll
            for (int d = 0; d < 4; d++) acc[i][j][d] = 0.0f;

    const int lr = tid >> 3;                    // 0..15
    const int lq = tid & 7;                     // 16B segment within 128B row
    auto issue_chunk = [&](int c) {
        const int s = c % NSTAGE;
        const uint32_t sA = smb + s * STAGE_BYTES;
        const uint32_t sB = sA + 16384;
        const __half* gA = A + (size_t)brow * DD + c * 64;
        const __half* gB = B + (size_t)bcol * DD + c * 64;
        #pragma unroll
        for (int i = 0; i < 8; i++) {
            int r = i * 16 + lr;
            uint32_t off = (uint32_t)(r * 128) + (uint32_t)(((lq ^ (r & 7)) << 4));
            const __half* pA = gA + (size_t)r * DD + lq * 8;
            const __half* pB = gB + (size_t)r * DD + lq * 8;
            asm volatile("cp.async.cg.shared.global [%0], [%1], 16;"
                         :: "r"(sA + off), "l"(pA) : "memory");
            asm volatile("cp.async.cg.shared.global [%0], [%1], 16;"
                         :: "r"(sB + off), "l"(pB) : "memory");
        }
        asm volatile("cp.async.commit_group;" ::: "memory");
    };

    const int t8 = lane >> 3;
    const int r8 = lane & 7;
    uint32_t aoff[4], boff[4];
    #pragma unroll
    for (int mf = 0; mf < 4; mf++)
        aoff[mf] = (uint32_t)((warp_m * 64 + mf * 16 + (t8 & 1) * 8 + r8) * 128);
    #pragma unroll
    for (int nf4 = 0; nf4 < 4; nf4++)
        boff[nf4] = (uint32_t)((warp_n * 64 + nf4 * 16 + (t8 >> 1) * 8 + r8) * 128) + 16384u;
    const int xa = (t8 >> 1);                   // A: k-half selector
    const int xb = (t8 & 1);                    // B: k-half selector

    // prologue: chunks 0,1 in flight; wait for chunk 0
    issue_chunk(0); issue_chunk(1);
    asm volatile("cp.async.wait_group 1;" ::: "memory");
    __syncthreads();

    for (int c = 0; c < NCHUNK; c++) {
        if (c + 2 < NCHUNK) issue_chunk(c + 2);

        const uint32_t base = smb + (c % NSTAGE) * STAGE_BYTES;

        #pragma unroll
        for (int ks = 0; ks < 4; ks++) {        // 4 x k16 = 64
            const uint32_t sgA = (uint32_t)(((ks * 2 + xa) ^ r8) << 4);
            const uint32_t sgB = (uint32_t)(((ks * 2 + xb) ^ r8) << 4);
            uint32_t b[8][2];
            #pragma unroll
            for (int nf4 = 0; nf4 < 4; nf4++)
                LDSM_X4(b[nf4 * 2][0], b[nf4 * 2][1],
                        b[nf4 * 2 + 1][0], b[nf4 * 2 + 1][1],
                        base + boff[nf4] + sgB);

            uint32_t acur[4], anxt[4];
            LDSM_X4(acur[0], acur[1], acur[2], acur[3], base + aoff[0] + sgA);
            #pragma unroll
            for (int mf = 0; mf < 4; mf++) {
                if (mf < 3)
                    LDSM_X4(anxt[0], anxt[1], anxt[2], anxt[3],
                            base + aoff[mf + 1] + sgA);
                #pragma unroll
                for (int nf = 0; nf < 8; nf++)
                    MMA_F16(acc[mf][nf],
                            acur[0], acur[1], acur[2], acur[3],
                            b[nf][0], b[nf][1]);
                #pragma unroll
                for (int k2 = 0; k2 < 4; k2++) acur[k2] = anxt[k2];
            }
        }

        if (c < NCHUNK - 2) {
            asm volatile("cp.async.wait_group 1;" ::: "memory");
            __syncthreads();
        } else if (c == NCHUNK - 2) {
            asm volatile("cp.async.wait_group 0;" ::: "memory");
            __syncthreads();
        }
    }

    // ----- epilogue: ALL-inclusive sums, no diagonal branches -----
    const int g = lane >> 2;                    // row within frag half
    const int q = lane & 3;                     // col pair
    float c2v[8];
    #pragma unroll
    for (int mf = 0; mf < 4; mf++) {
        c2v[mf * 2]     = g_c2[brow + warp_m * 64 + mf * 16 + g];
        c2v[mf * 2 + 1] = g_c2[brow + warp_m * 64 + mf * 16 + 8 + g];
    }
    float t2v[16];
    #pragma unroll
    for (int nf = 0; nf < 8; nf++) {
        t2v[nf * 2]     = g_t2[bcol + warp_n * 64 + nf * 8 + q * 2];
        t2v[nf * 2 + 1] = g_t2[bcol + warp_n * 64 + nf * 8 + q * 2 + 1];
    }

    float sexp = 0.0f;     // ALL-inclusive sum of p = 1/(1+d2)
    float slog = 0.0f;     // ALL-inclusive sum of logit = -log(1+d2)
    #pragma unroll
    for (int mf = 0; mf < 4; mf++) {
        #pragma unroll
        for (int h = 0; h < 2; h++) {
            const int row = brow + warp_m * 64 + mf * 16 + h * 8 + g;
            #pragma unroll
            for (int nf = 0; nf < 8; nf++) {
                const int col = bcol + warp_n * 64 + nf * 8 + q * 2;
                float dot0 = acc[mf][nf][h * 2];
                float dot1 = acc[mf][nf][h * 2 + 1];
                float u0 = fmaxf(c2v[mf * 2 + h] + t2v[nf * 2]     - 2.0f * dot0, 0.0f) + 1.0f;
                float u1 = fmaxf(c2v[mf * 2 + h] + t2v[nf * 2 + 1] - 2.0f * dot1, 0.0f) + 1.0f;
                float lg0 = -__logf(u0);
                float lg1 = -__logf(u1);
                slog += lg0 + lg1;
                sexp += __fdividef(1.0f, u0);
                sexp += __fdividef(1.0f, u1);
                *(__half2*)&g_l[(size_t)row * NR + col] =
                    __floats2half2_rn(lg0 + LSHIFT, lg1 + LSHIFT);
            }
        }
    }

    // reduce (sexp, slog): warp -> CTA -> bucketed atomic
    double se = (double)sexp;
    double sl = (double)slog;
    #pragma unroll
    for (int o = 16; o > 0; o >>= 1) {
        se += __shfl_down_sync(0xffffffffu, se, o);
        sl += __shfl_down_sync(0xffffffffu, sl, o);
    }
    double* red = (double*)dsm;
    __syncthreads();
    if (lane == 0) { red[wid] = se; red[4 + wid] = sl; }
    __syncthreads();
    if (tid == 0) {
        double t0 = 0.0, t1 = 0.0;
        #pragma unroll
        for (int w = 0; w < 4; w++) { t0 += red[w]; t1 += red[4 + w]; }
        int bk = (blockIdx.y * 64 + blockIdx.x) & 63;
        atomicAdd(&g_sexp_bucket[bk], t0);
        atomicAdd(&g_slog_bucket[bk], t1);
    }
}

// ---------------------------------------------------------------------------
// 3) fused: reduce buckets + diag-p subtraction -> LB, then diagonal stats.
//    One block, 256 threads.
// ---------------------------------------------------------------------------
__global__ void k_mid() {
    const int tid = threadIdx.x;
    __shared__ double r0[256], r1[256];
    __shared__ float  s_lb;

    // phase 1: log_baseline
    double s = 0.0, l = 0.0;
    if (tid < 64) { s = g_sexp_bucket[tid]; l = g_slog_bucket[tid]; }
    float sub = 0.0f;                          // sum of diagonal p
    for (int i = tid; i < NR; i += 256)
        sub += __fdividef(1.0f, 1.0f + g_dd2[i]);
    s -= (double)sub;

    r0[tid] = s; r1[tid] = l;
    __syncthreads();
    for (int st = 128; st > 0; st >>= 1) {
        if (tid < st) { r0[tid] += r0[tid + st]; r1[tid] += r1[tid + st]; }
        __syncthreads();
    }
    if (tid == 0) {
        double lb = log(r0[0]) - log((double)NR * (double)(NR - 1));
        g_acc[0] = r0[0];                      // S_exp over off-diagonal
        g_acc[4] = r1[0];                      // sum logit (all incl diag)
        g_acc[7] = lb;
        s_lb = (float)lb;
    }
    __syncthreads();

    // phase 2: diagonal statistics (exact fp32 d2)
    const float lbf = s_lb;
    float slog = 0.0f, ssig = 0.0f;
    int cnt = 0;
    for (int i = tid; i < NR; i += 256) {
        float d2 = g_dd2[i];
        float x = -log1pf(d2);
        float y = x - lbf;
        slog += x;
        ssig += 1.0f / (1.0f + expf(-y));
        cnt  += (y > 0.0f) ? 1 : 0;
    }
    r0[tid] = (double)slog; r1[tid] = (double)ssig;
    __shared__ int r2[256];
    r2[tid] = cnt;
    __syncthreads();
    for (int st = 128; st > 0; st >>= 1) {
        if (tid < st) { r0[tid] += r0[tid + st]; r1[tid] += r1[tid + st]; r2[tid] += r2[tid + st]; }
        __syncthreads();
    }
    if (tid == 0) { g_acc[1] = r0[0]; g_acc[2] = r1[0]; g_acc[3] = (double)r2[0]; }
}

// ---------------------------------------------------------------------------
// 4) streaming stats over all shifted logits (fp16) + last-block finalize.
//    Fully half2-native inner loop:
//      e  = h2exp(thr - l)          (exp(-(l-thr)) with folded negation)
//      sg = h2rcp(1 + e)            (sigmoid pair)
//      sacc2 += sg                  (<=32 adds/lane -> fp16-safe)
//      cacc2 += (l > thr) ? 1 : 0   (integer-exact in fp16)
// ---------------------------------------------------------------------------
#define STREAM_BLOCKS 4096

__global__ __launch_bounds__(256)
void k_stream(float* __restrict__ out) {
    const float thrf = (float)g_acc[7] + LSHIFT;
    const __half2 thr2 = __float2half2_rn(thrf);
    const __half2 one2 = __float2half2_rn(1.0f);
    const int tid = threadIdx.x;

    __half2 sacc2 = __float2half2_rn(0.0f);
    __half2 cacc2 = __float2half2_rn(0.0f);

    const size_t total8 = ((size_t)NR * NR) / 8;          // uint4 = 8 halves
    const size_t stride = (size_t)gridDim.x * blockDim.x; // 1,048,576
    const uint4* P8 = (const uint4*)g_l;

    // exactly 8 iterations per thread: 32 half2 adds per accumulator lane
    for (size_t i = (size_t)blockIdx.x * blockDim.x + tid; i < total8; i += stride) {
        uint4 v = __ldcs(&P8[i]);
        uint32_t w[4] = {v.x, v.y, v.z, v.w};
        #pragma unroll
        for (int j = 0; j < 4; j++) {
            __half2 hj = *(__half2*)&w[j];
            __half2 e  = h2exp(__hsub2(thr2, hj));
            __half2 sg = h2rcp(__hadd2(one2, e));
            sacc2 = __hadd2(sacc2, sg);
            cacc2 = __hadd2(cacc2, __hgt2(hj, thr2));
        }
    }

    float2 sf = __half22float2(sacc2);
    float2 cf = __half22float2(cacc2);
    float ssig = sf.x + sf.y;
    int   cnt  = (int)(cf.x + cf.y);

    __shared__ double r1[256];
    __shared__ int    r2[256];
    r1[tid] = (double)ssig; r2[tid] = cnt;
    __syncthreads();
    for (int s = 128; s > 0; s >>= 1) {
        if (tid < s) { r1[tid] += r1[tid + s]; r2[tid] += r2[tid + s]; }
        __syncthreads();
    }

    __shared__ int s_last;
    if (tid == 0) {
        atomicAdd(&g_acc[5], r1[0]);
        atomicAdd(&g_acc[6], (double)r2[0]);
        __threadfence();
        unsigned int t = atomicAdd(&g_ticket, 1u);
        s_last = (t == (unsigned int)(gridDim.x - 1)) ? 1 : 0;
    }
    __syncthreads();

    if (s_last && tid == 0) {
        __threadfence();
        const double Npos = (double)NR;
        const double Nneg = (double)NR * (double)(NR - 1);

        double LB   = g_acc[7];
        double sdl  = g_acc[1];
        double sds  = g_acc[2];
        double cntd = g_acc[3];
        double sal  = g_acc[4];
        double sas  = g_acc[5];
        double cnta = g_acc[6];

        double pos_mean  = sdl / Npos - LB;
        double neg_mean  = (sal - sdl) / Nneg - LB;
        double repulsion = exp(-LB) * g_acc[0] / Nneg;
        double loss      = -pos_mean + repulsion;
        double sig_pos   = sds / Npos;
        double sig_neg   = (sas - sds) / Nneg;

        double TP = cntd / Npos;
        double FP = (cnta - cntd) / Nneg;
        double TN = 1.0 - FP;
        double FN = 1.0 - TP;
        double accuracy  = (TP + TN) * 0.5;
        double precision = TP / (TP + FP);
        double npv       = TN / (TN + FN);
        double apv       = (precision + npv) * 0.5;

        out[0]  = (float)loss;
        out[1]  = (float)pos_mean;
        out[2]  = (float)neg_mean;
        out[3]  = (float)sig_pos;
        out[4]  = (float)sig_neg;
        out[5]  = (float)LB;
        out[6]  = (float)accuracy;
        out[7]  = (float)precision;
        out[8]  = (float)npv;
        out[9]  = (float)apv;
        out[10] = (float)TP;
        out[11] = (float)TN;
    }
}

// ---------------------------------------------------------------------------
// launch
// ---------------------------------------------------------------------------
extern "C" void kernel_launch(void* const* d_in, const int* in_sizes, int n_in,
                              void* d_out, int out_size) {
    const float* C = (const float*)d_in[0];
    const float* T = (const float*)d_in[1];
    float* out = (float*)d_out;

    static int configured = 0;
    if (!configured) {
        cudaFuncSetAttribute(k_gemm_tc, cudaFuncAttributeMaxDynamicSharedMemorySize, SMEM_DYN);
        configured = 1;
    }

    k_init<<<1, 64>>>();                         // launch 0
    k_prepC<<<NR, 128>>>(C);                     // launch 1
    k_prepT<<<NR, 128>>>(T);                     // launch 2
    dim3 grid(NR / 128, NR / 128);
    k_gemm_tc<<<grid, 128, SMEM_DYN>>>();        // launch 3  <- ncu capture slot
    k_mid<<<1, 256>>>();                         // launch 4
    k_stream<<<STREAM_BLOCKS, 256>>>(out);       // launch 5 (finalize fused)
}

// round 17
// speedup vs baseline: 1.1762x; 1.0184x over previous
#include <cuda_runtime.h>
#include <cuda_fp16.h>
#include <cstdint>
#include <cstddef>

#define NR 8192
#define DD 512
#define LSHIFT 6.931472f   // ~ln(1024): centers logits near 0 for fp16 storage

// ---------------------------------------------------------------------------
// Device scratch (static — no cudaMalloc allowed)
// ---------------------------------------------------------------------------
__device__ __half g_l[(size_t)NR * NR];        // 134 MB: logit + LSHIFT, fp16
__device__ float  g_dd2[NR];                   // exact fp32 diagonal d2
__device__ __half g_ca[(size_t)NR * DD];       // fp16-rounded context
__device__ __half g_tb[(size_t)NR * DD];       // fp16-rounded target
__device__ float  g_c2[NR];                    // ||c_h||^2 of rounded values
__device__ float  g_t2[NR];
// [0]=S_exp_off [1]=sum_logit_diag [2]=sum_sig_diag [3]=cnt_diag
// [4]=sum_logit_all [5]=sum_sig_all [6]=cnt_all [7]=log_baseline
__device__ double g_acc[16];
__device__ double g_sexp_bucket[64];
__device__ double g_slog_bucket[64];
__device__ unsigned int g_ticket;

// ---------------------------------------------------------------------------
// helpers
// ---------------------------------------------------------------------------
__device__ __forceinline__ uint32_t smem_u32(const void* p) {
    uint32_t a;
    asm("{ .reg .u64 t; cvta.to.shared.u64 t, %1; cvt.u32.u64 %0, t; }"
        : "=r"(a) : "l"(p));
    return a;
}

#define LDSM_X4(r0, r1, r2, r3, addr)                                   \
    asm volatile("ldmatrix.sync.aligned.m8n8.x4.shared.b16 "            \
                 "{%0,%1,%2,%3}, [%4];"                                 \
                 : "=r"(r0), "=r"(r1), "=r"(r2), "=r"(r3) : "r"(addr))

#define MMA_F16(d, a0, a1, a2, a3, b0, b1)                              \
    asm volatile("mma.sync.aligned.m16n8k16.row.col.f32.f16.f16.f32 "   \
                 "{%0,%1,%2,%3}, {%4,%5,%6,%7}, {%8,%9}, {%0,%1,%2,%3};"\
                 : "+f"((d)[0]), "+f"((d)[1]), "+f"((d)[2]), "+f"((d)[3])\
                 : "r"(a0), "r"(a1), "r"(a2), "r"(a3), "r"(b0), "r"(b1))

// ---------------------------------------------------------------------------
// 1) fused prep (+ accumulator init in block 0): each block handles row i of
//    BOTH C and T. fp16-rounded copies, squared norms of rounded values,
//    diagonal d2 directly from registers.
//    The init is consumed only by LATER launches -> no ordering hazard.
// ---------------------------------------------------------------------------
__global__ void k_prepCT(const float* __restrict__ C, const float* __restrict__ T) {
    int row = blockIdx.x;

    if (row == 0) {
        if (threadIdx.x < 16) g_acc[threadIdx.x] = 0.0;
        if (threadIdx.x < 64) { g_sexp_bucket[threadIdx.x] = 0.0; g_slog_bucket[threadIdx.x] = 0.0; }
        if (threadIdx.x == 0) g_ticket = 0u;
    }

    float4 vc = ((const float4*)(C + (size_t)row * DD))[threadIdx.x];
    __half2 hc0 = __floats2half2_rn(vc.x, vc.y);
    __half2 hc1 = __floats2half2_rn(vc.z, vc.w);
    ((uint2*)(g_ca + (size_t)row * DD))[threadIdx.x] =
        make_uint2(*(uint32_t*)&hc0, *(uint32_t*)&hc1);

    float4 vt = ((const float4*)(T + (size_t)row * DD))[threadIdx.x];
    __half2 ht0 = __floats2half2_rn(vt.x, vt.y);
    __half2 ht1 = __floats2half2_rn(vt.z, vt.w);
    ((uint2*)(g_tb + (size_t)row * DD))[threadIdx.x] =
        make_uint2(*(uint32_t*)&ht0, *(uint32_t*)&ht1);

    float2 c0 = __half22float2(hc0), c1 = __half22float2(hc1);
    float2 t0 = __half22float2(ht0), t1 = __half22float2(ht1);

    float sc = c0.x * c0.x + c0.y * c0.y + c1.x * c1.x + c1.y * c1.y;
    float st = t0.x * t0.x + t0.y * t0.y + t1.x * t1.x + t1.y * t1.y;
    float e0 = c0.x - t0.x, e1 = c0.y - t0.y;
    float e2 = c1.x - t1.x, e3 = c1.y - t1.y;
    float d  = e0 * e0 + e1 * e1 + e2 * e2 + e3 * e3;

    #pragma unroll
    for (int o = 16; o > 0; o >>= 1) {
        sc += __shfl_down_sync(0xffffffffu, sc, o);
        st += __shfl_down_sync(0xffffffffu, st, o);
        d  += __shfl_down_sync(0xffffffffu, d, o);
    }
    __shared__ float wc[4], wt[4], wd[4];
    if ((threadIdx.x & 31) == 0) {
        wc[threadIdx.x >> 5] = sc; wt[threadIdx.x >> 5] = st; wd[threadIdx.x >> 5] = d;
    }
    __syncthreads();
    if (threadIdx.x == 0) {
        g_c2[row]  = wc[0] + wc[1] + wc[2] + wc[3];
        g_t2[row]  = wt[0] + wt[1] + wt[2] + wt[3];
        g_dd2[row] = wd[0] + wd[1] + wd[2] + wd[3];
    }
}

// ---------------------------------------------------------------------------
// 2) fp16 mma.sync GEMM (C @ T^T), 128x128x64 CTA tile, 128 threads,
//    4 warps (2x2) of 64x64. Single-sync software pipeline + A-frag pipelining.
//    (EXACT R11/R16-best mainloop — protected asset, 236 us measured.)
// ---------------------------------------------------------------------------
#define NSTAGE 3
#define STAGE_BYTES 32768                       // A 16KB + B 16KB
#define SMEM_DYN (NSTAGE * STAGE_BYTES)         // 96 KB
#define NCHUNK 8                                // 512 / 64

__global__ __launch_bounds__(128, 2)
void k_gemm_tc() {
    extern __shared__ char dsm[];
    const uint32_t smb = smem_u32(dsm);
    const int tid  = threadIdx.x;
    const int wid  = tid >> 5;
    const int lane = tid & 31;
    const int warp_m = wid >> 1;                // 0..1 (64 rows each)
    const int warp_n = wid & 1;                 // 0..1 (64 cols each)
    const int brow = blockIdx.y * 128;
    const int bcol = blockIdx.x * 128;

    const __half* A = g_ca;
    const __half* B = g_tb;

    float acc[4][8][4];
    #pragma unroll
    for (int i = 0; i < 4; i++)
        #pragma unroll
        for (int j = 0; j < 8; j++)
            #pragma unroll
            for (int d = 0; d < 4; d++) acc[i][j][d] = 0.0f;

    const int lr = tid >> 3;                    // 0..15
    const int lq = tid & 7;                     // 16B segment within 128B row
    auto issue_chunk = [&](int c) {
        const int s = c % NSTAGE;
        const uint32_t sA = smb + s * STAGE_BYTES;
        const uint32_t sB = sA + 16384;
        const __half* gA = A + (size_t)brow * DD + c * 64;
        const __half* gB = B + (size_t)bcol * DD + c * 64;
        #pragma unroll
        for (int i = 0; i < 8; i++) {
            int r = i * 16 + lr;
            uint32_t off = (uint32_t)(r * 128) + (uint32_t)(((lq ^ (r & 7)) << 4));
            const __half* pA = gA + (size_t)r * DD + lq * 8;
            const __half* pB = gB + (size_t)r * DD + lq * 8;
            asm volatile("cp.async.cg.shared.global [%0], [%1], 16;"
                         :: "r"(sA + off), "l"(pA) : "memory");
            asm volatile("cp.async.cg.shared.global [%0], [%1], 16;"
                         :: "r"(sB + off), "l"(pB) : "memory");
        }
        asm volatile("cp.async.commit_group;" ::: "memory");
    };

    const int t8 = lane >> 3;
    const int r8 = lane & 7;
    uint32_t aoff[4], boff[4];
    #pragma unroll
    for (int mf = 0; mf < 4; mf++)
        aoff[mf] = (uint32_t)((warp_m * 64 + mf * 16 + (t8 & 1) * 8 + r8) * 128);
    #pragma unroll
    for (int nf4 = 0; nf4 < 4; nf4++)
        boff[nf4] = (uint32_t)((warp_n * 64 + nf4 * 16 + (t8 >> 1) * 8 + r8) * 128) + 16384u;
    const int xa = (t8 >> 1);                   // A: k-half selector
    const int xb = (t8 & 1);                    // B: k-half selector

    // prologue: chunks 0,1 in flight; wait for chunk 0
    issue_chunk(0); issue_chunk(1);
    asm volatile("cp.async.wait_group 1;" ::: "memory");
    __syncthreads();

    for (int c = 0; c < NCHUNK; c++) {
        if (c + 2 < NCHUNK) issue_chunk(c + 2);

        const uint32_t base = smb + (c % NSTAGE) * STAGE_BYTES;

        #pragma unroll
        for (int ks = 0; ks < 4; ks++) {        // 4 x k16 = 64
            const uint32_t sgA = (uint32_t)(((ks * 2 + xa) ^ r8) << 4);
            const uint32_t sgB = (uint32_t)(((ks * 2 + xb) ^ r8) << 4);
            uint32_t b[8][2];
            #pragma unroll
            for (int nf4 = 0; nf4 < 4; nf4++)
                LDSM_X4(b[nf4 * 2][0], b[nf4 * 2][1],
                        b[nf4 * 2 + 1][0], b[nf4 * 2 + 1][1],
                        base + boff[nf4] + sgB);

            uint32_t acur[4], anxt[4];
            LDSM_X4(acur[0], acur[1], acur[2], acur[3], base + aoff[0] + sgA);
            #pragma unroll
            for (int mf = 0; mf < 4; mf++) {
                if (mf < 3)
                    LDSM_X4(anxt[0], anxt[1], anxt[2], anxt[3],
                            base + aoff[mf + 1] + sgA);
                #pragma unroll
                for (int nf = 0; nf < 8; nf++)
                    MMA_F16(acc[mf][nf],
                            acur[0], acur[1], acur[2], acur[3],
                            b[nf][0], b[nf][1]);
                #pragma unroll
                for (int k2 = 0; k2 < 4; k2++) acur[k2] = anxt[k2];
            }
        }

        if (c < NCHUNK - 2) {
            asm volatile("cp.async.wait_group 1;" ::: "memory");
            __syncthreads();
        } else if (c == NCHUNK - 2) {
            asm volatile("cp.async.wait_group 0;" ::: "memory");
            __syncthreads();
        }
    }

    // ----- epilogue: ALL-inclusive sums, no diagonal branches -----
    const int g = lane >> 2;                    // row within frag half
    const int q = lane & 3;                     // col pair
    float c2v[8];
    #pragma unroll
    for (int mf = 0; mf < 4; mf++) {
        c2v[mf * 2]     = g_c2[brow + warp_m * 64 + mf * 16 + g];
        c2v[mf * 2 + 1] = g_c2[brow + warp_m * 64 + mf * 16 + 8 + g];
    }
    float t2v[16];
    #pragma unroll
    for (int nf = 0; nf < 8; nf++) {
        t2v[nf * 2]     = g_t2[bcol + warp_n * 64 + nf * 8 + q * 2];
        t2v[nf * 2 + 1] = g_t2[bcol + warp_n * 64 + nf * 8 + q * 2 + 1];
    }

    float sexp = 0.0f;     // ALL-inclusive sum of p = 1/(1+d2)
    float slog = 0.0f;     // ALL-inclusive sum of logit = -log(1+d2)
    #pragma unroll
    for (int mf = 0; mf < 4; mf++) {
        #pragma unroll
        for (int h = 0; h < 2; h++) {
            const int row = brow + warp_m * 64 + mf * 16 + h * 8 + g;
            #pragma unroll
            for (int nf = 0; nf < 8; nf++) {
                const int col = bcol + warp_n * 64 + nf * 8 + q * 2;
                float dot0 = acc[mf][nf][h * 2];
                float dot1 = acc[mf][nf][h * 2 + 1];
                float u0 = fmaxf(c2v[mf * 2 + h] + t2v[nf * 2]     - 2.0f * dot0, 0.0f) + 1.0f;
                float u1 = fmaxf(c2v[mf * 2 + h] + t2v[nf * 2 + 1] - 2.0f * dot1, 0.0f) + 1.0f;
                float lg0 = -__logf(u0);
                float lg1 = -__logf(u1);
                slog += lg0 + lg1;
                sexp += __fdividef(1.0f, u0);
                sexp += __fdividef(1.0f, u1);
                *(__half2*)&g_l[(size_t)row * NR + col] =
                    __floats2half2_rn(lg0 + LSHIFT, lg1 + LSHIFT);
            }
        }
    }

    // reduce (sexp, slog): warp -> CTA -> bucketed atomic
    double se = (double)sexp;
    double sl = (double)slog;
    #pragma unroll
    for (int o = 16; o > 0; o >>= 1) {
        se += __shfl_down_sync(0xffffffffu, se, o);
        sl += __shfl_down_sync(0xffffffffu, sl, o);
    }
    double* red = (double*)dsm;
    __syncthreads();
    if (lane == 0) { red[wid] = se; red[4 + wid] = sl; }
    __syncthreads();
    if (tid == 0) {
        double t0 = 0.0, t1 = 0.0;
        #pragma unroll
        for (int w = 0; w < 4; w++) { t0 += red[w]; t1 += red[4 + w]; }
        int bk = (blockIdx.y * 64 + blockIdx.x) & 63;
        atomicAdd(&g_sexp_bucket[bk], t0);
        atomicAdd(&g_slog_bucket[bk], t1);
    }
}

// ---------------------------------------------------------------------------
// 3) fused: reduce buckets + diag-p subtraction -> LB, then diagonal stats.
//    One block, 256 threads.
// ---------------------------------------------------------------------------
__global__ void k_mid() {
    const int tid = threadIdx.x;
    __shared__ double r0[256], r1[256];
    __shared__ float  s_lb;

    // phase 1: log_baseline
    double s = 0.0, l = 0.0;
    if (tid < 64) { s = g_sexp_bucket[tid]; l = g_slog_bucket[tid]; }
    float sub = 0.0f;                          // sum of diagonal p
    for (int i = tid; i < NR; i += 256)
        sub += __fdividef(1.0f, 1.0f + g_dd2[i]);
    s -= (double)sub;

    r0[tid] = s; r1[tid] = l;
    __syncthreads();
    for (int st = 128; st > 0; st >>= 1) {
        if (tid < st) { r0[tid] += r0[tid + st]; r1[tid] += r1[tid + st]; }
        __syncthreads();
    }
    if (tid == 0) {
        double lb = log(r0[0]) - log((double)NR * (double)(NR - 1));
        g_acc[0] = r0[0];                      // S_exp over off-diagonal
        g_acc[4] = r1[0];                      // sum logit (all incl diag)
        g_acc[7] = lb;
        s_lb = (float)lb;
    }
    __syncthreads();

    // phase 2: diagonal statistics (exact fp32 d2)
    const float lbf = s_lb;
    float slog = 0.0f, ssig = 0.0f;
    int cnt = 0;
    for (int i = tid; i < NR; i += 256) {
        float d2 = g_dd2[i];
        float x = -log1pf(d2);
        float y = x - lbf;
        slog += x;
        ssig += 1.0f / (1.0f + expf(-y));
        cnt  += (y > 0.0f) ? 1 : 0;
    }
    r0[tid] = (double)slog; r1[tid] = (double)ssig;
    __shared__ int r2[256];
    r2[tid] = cnt;
    __syncthreads();
    for (int st = 128; st > 0; st >>= 1) {
        if (tid < st) { r0[tid] += r0[tid + st]; r1[tid] += r1[tid + st]; r2[tid] += r2[tid + st]; }
        __syncthreads();
    }
    if (tid == 0) { g_acc[1] = r0[0]; g_acc[2] = r1[0]; g_acc[3] = (double)r2[0]; }
}

// ---------------------------------------------------------------------------
// 4) streaming stats over all shifted logits (fp16) + last-block finalize.
//    Fully half2-native inner loop (R16-winning version).
// ---------------------------------------------------------------------------
#define STREAM_BLOCKS 4096

__global__ __launch_bounds__(256)
void k_stream(float* __restrict__ out) {
    const float thrf = (float)g_acc[7] + LSHIFT;
    const __half2 thr2 = __float2half2_rn(thrf);
    const __half2 one2 = __float2half2_rn(1.0f);
    const int tid = threadIdx.x;

    __half2 sacc2 = __float2half2_rn(0.0f);
    __half2 cacc2 = __float2half2_rn(0.0f);

    const size_t total8 = ((size_t)NR * NR) / 8;          // uint4 = 8 halves
    const size_t stride = (size_t)gridDim.x * blockDim.x; // 1,048,576
    const uint4* P8 = (const uint4*)g_l;

    for (size_t i = (size_t)blockIdx.x * blockDim.x + tid; i < total8; i += stride) {
        uint4 v = __ldcs(&P8[i]);
        uint32_t w[4] = {v.x, v.y, v.z, v.w};
        #pragma unroll
        for (int j = 0; j < 4; j++) {
            __half2 hj = *(__half2*)&w[j];
            __half2 e  = h2exp(__hsub2(thr2, hj));
            __half2 sg = h2rcp(__hadd2(one2, e));
            sacc2 = __hadd2(sacc2, sg);
            cacc2 = __hadd2(cacc2, __hgt2(hj, thr2));
        }
    }

    float2 sf = __half22float2(sacc2);
    float2 cf = __half22float2(cacc2);
    float ssig = sf.x + sf.y;
    int   cnt  = (int)(cf.x + cf.y);

    __shared__ double r1[256];
    __shared__ int    r2[256];
    r1[tid] = (double)ssig; r2[tid] = cnt;
    __syncthreads();
    for (int s = 128; s > 0; s >>= 1) {
        if (tid < s) { r1[tid] += r1[tid + s]; r2[tid] += r2[tid + s]; }
        __syncthreads();
    }

    __shared__ int s_last;
    if (tid == 0) {
        atomicAdd(&g_acc[5], r1[0]);
        atomicAdd(&g_acc[6], (double)r2[0]);
        __threadfence();
        unsigned int t = atomicAdd(&g_ticket, 1u);
        s_last = (t == (unsigned int)(gridDim.x - 1)) ? 1 : 0;
    }
    __syncthreads();

    if (s_last && tid == 0) {
        __threadfence();
        const double Npos = (double)NR;
        const double Nneg = (double)NR * (double)(NR - 1);

        double LB   = g_acc[7];
        double sdl  = g_acc[1];
        double sds  = g_acc[2];
        double cntd = g_acc[3];
        double sal  = g_acc[4];
        double sas  = g_acc[5];
        double cnta = g_acc[6];

        double pos_mean  = sdl / Npos - LB;
        double neg_mean  = (sal - sdl) / Nneg - LB;
        double repulsion = exp(-LB) * g_acc[0] / Nneg;
        double loss      = -pos_mean + repulsion;
        double sig_pos   = sds / Npos;
        double sig_neg   = (sas - sds) / Nneg;

        double TP = cntd / Npos;
        double FP = (cnta - cntd) / Nneg;
        double TN = 1.0 - FP;
        double FN = 1.0 - TP;
        double accuracy  = (TP + TN) * 0.5;
        double precision = TP / (TP + FP);
        double npv       = TN / (TN + FN);
        double apv       = (precision + npv) * 0.5;

        out[0]  = (float)loss;
        out[1]  = (float)pos_mean;
        out[2]  = (float)neg_mean;
        out[3]  = (float)sig_pos;
        out[4]  = (float)sig_neg;
        out[5]  = (float)LB;
        out[6]  = (float)accuracy;
        out[7]  = (float)precision;
        out[8]  = (float)npv;
        out[9]  = (float)apv;
        out[10] = (float)TP;
        out[11] = (float)TN;
    }
}

// ---------------------------------------------------------------------------
// launch
// ---------------------------------------------------------------------------
extern "C" void kernel_launch(void* const* d_in, const int* in_sizes, int n_in,
                              void* d_out, int out_size) {
    const float* C = (const float*)d_in[0];
    const float* T = (const float*)d_in[1];
    float* out = (float*)d_out;

    static int configured = 0;
    if (!configured) {
        cudaFuncSetAttribute(k_gemm_tc, cudaFuncAttributeMaxDynamicSharedMemorySize, SMEM_DYN);
        configured = 1;
    }

    k_prepCT<<<NR, 128>>>(C, T);                 // launch 0 (init fused)
    dim3 grid(NR / 128, NR / 128);
    k_gemm_tc<<<grid, 128, SMEM_DYN>>>();        // launch 1
    k_mid<<<1, 256>>>();                         // launch 2
    k_stream<<<STREAM_BLOCKS, 256>>>(out);       // launch 3 <- ncu capture slot
}